// round 13
// baseline (speedup 1.0000x reference)
#include <cuda_runtime.h>
#include <cuda_bf16.h>
#include <stdint.h>
#include <math.h>

#define IN_SZ   3072
#define CORE    1024
#define OUT_N   100
#define OUT_PAD 128
#define BATCH   8192
#define STAGES  3
#define STG_OP  16384
#define SMEM_BYTES (STAGES * 2 * STG_OP)
#define NROW    64            // 8192/128 row blocks
#define T_L1    512           // 64 rowblk x 8 ntiles
#define T_L2    512
#define T_L3    64
#define T_ALL   (T_L1 + T_L2 + T_L3)
#define GRID_P  296           // 148 SM x 2 CTA

__device__ int g_mode;
__device__ int g_tilectr;
__device__ int g_rowdone[NROW];   // L1 n-tiles completed per row block
__device__ int g_row2done[NROW];  // L2 n-tiles completed per row block

__device__ __align__(16) int8_t g_WiT[CORE * IN_SZ];
__device__ __align__(16) int8_t g_WcT[CORE * CORE];
__device__ __align__(16) int8_t g_WoT[OUT_PAD * CORE];
__device__ __align__(16) int    g_bi[CORE];
__device__ __align__(16) int    g_bc[CORE];
__device__ __align__(16) int    g_bo[OUT_PAD];
__device__ __align__(16) int8_t g_in8[(size_t)BATCH * IN_SZ];
__device__ __align__(16) int8_t g_h8[(size_t)BATCH * CORE];
__device__ __align__(16) int8_t g_A2[(size_t)BATCH * CORE];
__device__ __align__(16) int8_t g_H2[(size_t)BATCH * CORE];

__device__ __forceinline__ uint32_t smem_u32(const void* p) {
    uint32_t a;
    asm("{ .reg .u64 t; cvta.to.shared.u64 t, %1; cvt.u32.u64 %0, t; }" : "=r"(a) : "l"(p));
    return a;
}
__device__ __forceinline__ void cpasync16(unsigned dst, const void* src) {
    asm volatile("cp.async.cg.shared.global [%0], [%1], 16;" :: "r"(dst), "l"(src));
}
__device__ __forceinline__ int ldval(const void* src, long i, int m) {
    if (m == 0) return (int)((const int8_t*)src)[i];
    if (m == 1) return (int)((const float*)src)[i];
    if (m == 2) return ((const int*)src)[i];
    return (int)__bfloat162float(((const __nv_bfloat16*)src)[i]);
}

// launch 0: dtype detection + flag reset (graph-replay safe)
__global__ void detect_mode(const void* w, int unit) {
    int t = threadIdx.x;
    if (t < NROW) { g_rowdone[t] = 0; g_row2done[t] = 0; }
    if (t == 0) g_tilectr = 0;
    if (unit == 2) { if (t == 0) g_mode = 3; return; }
    unsigned r = ((const unsigned*)w)[t * 101];
    int vi = (int)r;
    bool okI = (vi >= -10 && vi <= 10);
    float f = __int_as_float(r);
    bool okF = (isfinite(f) && f == truncf(f) && fabsf(f) <= 10.0f &&
                (f == 0.0f || fabsf(f) >= 1.0f));
    bool okB = true;
    for (int h = 0; h < 2; h++) {
        unsigned hf = (h == 0) ? (r & 0xFFFFu) : (r >> 16);
        float fb = __int_as_float(hf << 16);
        if (!(isfinite(fb) && fb == truncf(fb) && fabsf(fb) <= 10.0f &&
              (fb == 0.0f || fabsf(fb) >= 1.0f))) okB = false;
    }
    int aI = __syncthreads_and((int)okI);
    int aF = __syncthreads_and((int)okF);
    int aB = __syncthreads_and((int)okB);
    if (t == 0)
        g_mode = (unit == 4) ? (aI ? 2 : 1) : (aI ? 2 : (aF ? 1 : (aB ? 3 : 0)));
}

__global__ void conv_acts(const void* __restrict__ inp, const void* __restrict__ hid) {
    const int m = g_mode;
    if (m == 0) return;
    long i = (long)blockIdx.x * blockDim.x + threadIdx.x;
    const long NI = (long)BATCH * IN_SZ;
    if (i < NI) g_in8[i] = (int8_t)ldval(inp, i, m);
    else {
        long j = i - NI;
        if (j < (long)BATCH * CORE) g_h8[j] = (int8_t)ldval(hid, j, m);
    }
}

#define TWI 3072
#define TWC 1024
#define TWO 128
__global__ void prep_wb(const void* __restrict__ Wi, const void* __restrict__ ei,
                        const void* __restrict__ Wc, const void* __restrict__ ec,
                        const void* __restrict__ Wo, const void* __restrict__ eo,
                        const void* __restrict__ bi, const void* __restrict__ ebi,
                        const void* __restrict__ bc, const void* __restrict__ ebc,
                        const void* __restrict__ bo, const void* __restrict__ ebo) {
    const int m = g_mode;
    const int b = blockIdx.x;
    const int tx = threadIdx.x, ty = threadIdx.y;
    const void *W, *E;
    int8_t* dst;
    int Kdim, Ncols, kt, nt;
    if (b < TWI) {
        W = Wi; E = ei; dst = g_WiT; Kdim = IN_SZ; Ncols = CORE;
        kt = b % (IN_SZ / 32); nt = b / (IN_SZ / 32);
    } else if (b < TWI + TWC) {
        int r = b - TWI;
        W = Wc; E = ec; dst = g_WcT; Kdim = CORE; Ncols = CORE;
        kt = r % 32; nt = r / 32;
    } else if (b < TWI + TWC + TWO) {
        int r = b - TWI - TWC;
        W = Wo; E = eo; dst = g_WoT; Kdim = CORE; Ncols = OUT_N;
        kt = r % 32; nt = r / 32;
    } else {
        int t = (b - TWI - TWC - TWO) * 256 + ty * 32 + tx;
        if (t < CORE) g_bi[t] = (int)(int8_t)(ldval(bi, t, m) + ldval(ebi, t, m));
        else if (t < 2 * CORE) {
            int i = t - CORE;
            g_bc[i] = (int)(int8_t)(ldval(bc, i, m) + ldval(ebc, i, m));
        } else if (t < 2 * CORE + OUT_PAD) {
            int i = t - 2 * CORE;
            g_bo[i] = (i < OUT_N) ? (int)(int8_t)(ldval(bo, i, m) + ldval(ebo, i, m)) : 0;
        }
        return;
    }
    __shared__ int8_t s[32][33];
    const int kb = kt * 32, nb = nt * 32;
#pragma unroll
    for (int i = 0; i < 32; i += 8) {
        int k = kb + ty + i, n = nb + tx;
        int8_t v = 0;
        if (n < Ncols) {
            long idx = (long)k * Ncols + n;
            v = (int8_t)(ldval(W, idx, m) + ldval(E, idx, m));
        }
        s[ty + i][tx] = v;
    }
    __syncthreads();
#pragma unroll
    for (int i = 0; i < 32; i += 8) {
        int n = nb + ty + i, k = kb + tx;
        dst[(size_t)n * Kdim + k] = s[tx][ty + i];
    }
}

// ---------------- fused persistent GEMM: all 3 layers, atomic tile queue ----------------
__global__ void __launch_bounds__(256, 2)
gemm_all(const int8_t* __restrict__ rawIn, const int8_t* __restrict__ rawHid,
         void* __restrict__ Dout, int mode_out) {
    extern __shared__ __align__(16) int8_t dyn[];
    __shared__ int sh_id;

    const int tid = threadIdx.x, lane = tid & 31, wid = tid >> 5;
    const int wm = (wid & 1) * 64, wn = (wid >> 1) * 32;
    const int r0  = tid >> 3;
    const int seg = (tid & 7) << 4;
    const int swz = seg ^ ((r0 & 7) << 4);
    const unsigned uS = smem_u32(dyn);
    const unsigned uB = uS + STAGES * STG_OP;

    const int mode = g_mode;
    const int8_t* inA = (mode != 0) ? g_in8 : rawIn;
    const int8_t* hidA = (mode != 0) ? g_h8 : rawHid;

    for (;;) {
        if (tid == 0) sh_id = atomicAdd(&g_tilectr, 1);
        __syncthreads();
        const int id = sh_id;
        __syncthreads();   // protect sh_id before next overwrite
        if (id >= T_ALL) break;

        // ---- decode tile ----
        int layer, mblk, nblk;
        const int8_t *A, *Bt;
        const int* bias;
        int K;
        if (id < T_L1) {
            layer = 1; mblk = id >> 3; nblk = id & 7;
            A = inA; Bt = g_WiT; bias = g_bi; K = IN_SZ;
        } else if (id < T_L1 + T_L2) {
            int j = id - T_L1;
            layer = 2; mblk = j >> 3; nblk = j & 7;
            A = g_A2; Bt = g_WcT; bias = g_bc; K = CORE;
        } else {
            layer = 3; mblk = id - T_L1 - T_L2; nblk = 0;
            A = g_H2; Bt = g_WoT; bias = g_bo; K = CORE;
        }
        const int m0 = mblk * 128, n0 = nblk * 128;

        // ---- dependency wait ----
        if (layer == 2) {
            if (tid == 0) while (atomicAdd(&g_rowdone[mblk], 0) < 8) __nanosleep(128);
            __syncthreads();
        } else if (layer == 3) {
            if (tid == 0) while (atomicAdd(&g_row2done[mblk], 0) < 8) __nanosleep(128);
            __syncthreads();
        }

        // ---- mainloop ----
        const int8_t* gA = A + (size_t)(m0 + r0) * K + seg;
        const int8_t* gB = Bt + (size_t)(n0 + r0) * K + seg;
        const long rs32 = 32L * K;
        const int nk = K >> 7;

        int acc[4][4][4];
#pragma unroll
        for (int a = 0; a < 4; a++)
#pragma unroll
            for (int b = 0; b < 4; b++)
#pragma unroll
                for (int c = 0; c < 4; c++) acc[a][b][c] = 0;

#define LOADT(st, kt)                                                     \
        do {                                                              \
            const unsigned _a = uS + (st) * STG_OP;                       \
            const unsigned _b = uB + (st) * STG_OP;                       \
            const long _o = (long)((kt) << 7);                            \
            _Pragma("unroll")                                             \
            for (int _i = 0; _i < 4; _i++) {                              \
                const unsigned _d = (_i * 32 + r0) * 128 + swz;           \
                cpasync16(_a + _d, gA + _o + _i * rs32);                  \
                cpasync16(_b + _d, gB + _o + _i * rs32);                  \
            }                                                             \
            asm volatile("cp.async.commit_group;");                       \
        } while (0)

        LOADT(0, 0);
        if (nk > 1) LOADT(1, 1);

        for (int kt = 0; kt < nk; kt++) {
            const int cur = kt % STAGES;
            asm volatile("cp.async.wait_group 1;");
            __syncthreads();
            if (kt + 2 < nk) LOADT((kt + 2) % STAGES, kt + 2);
            const unsigned ab = uS + cur * STG_OP;
            const unsigned bb = uB + cur * STG_OP;
#pragma unroll
            for (int ks = 0; ks < 128; ks += 32) {
                uint32_t af[4][4], bf[4][2];
#pragma unroll
                for (int mf = 0; mf < 4; mf++) {
                    const int ra = wm + mf * 16 + (lane & 15);
                    const int ca = ks + ((lane >> 4) << 4);
                    const unsigned p = ab + ra * 128 + (ca ^ ((ra & 7) << 4));
                    asm volatile("ldmatrix.sync.aligned.m8n8.x4.shared.b16 {%0,%1,%2,%3}, [%4];"
                                 : "=r"(af[mf][0]), "=r"(af[mf][1]), "=r"(af[mf][2]), "=r"(af[mf][3]) : "r"(p));
                }
#pragma unroll
                for (int nf = 0; nf < 4; nf++) {
                    const int rb = wn + nf * 8 + (lane & 7);
                    const int cb = ks + (((lane >> 3) & 1) << 4);
                    const unsigned p = bb + rb * 128 + (cb ^ ((rb & 7) << 4));
                    asm volatile("ldmatrix.sync.aligned.m8n8.x2.shared.b16 {%0,%1}, [%2];"
                                 : "=r"(bf[nf][0]), "=r"(bf[nf][1]) : "r"(p));
                }
#pragma unroll
                for (int mf = 0; mf < 4; mf++)
#pragma unroll
                    for (int nf = 0; nf < 4; nf++)
                        asm volatile("mma.sync.aligned.m16n8k32.row.col.s32.s8.s8.s32 "
                                     "{%0,%1,%2,%3}, {%4,%5,%6,%7}, {%8,%9}, {%0,%1,%2,%3};"
                                     : "+r"(acc[mf][nf][0]), "+r"(acc[mf][nf][1]),
                                       "+r"(acc[mf][nf][2]), "+r"(acc[mf][nf][3])
                                     : "r"(af[mf][0]), "r"(af[mf][1]), "r"(af[mf][2]), "r"(af[mf][3]),
                                       "r"(bf[nf][0]), "r"(bf[nf][1]));
            }
        }
#undef LOADT
        asm volatile("cp.async.wait_group 0;");

        // ---- epilogue ----
        const int rr = lane >> 2, cq = (lane & 3) * 2;
#pragma unroll
        for (int mf = 0; mf < 4; mf++)
#pragma unroll
            for (int nf = 0; nf < 4; nf++)
#pragma unroll
                for (int half = 0; half < 2; half++) {
#pragma unroll
                    for (int e = 0; e < 2; e++) {
                        const int m = m0 + wm + mf * 16 + rr + half * 8;
                        const int n = n0 + wn + nf * 8 + cq + e;
                        const int v = acc[mf][nf][half * 2 + e];
                        int8_t r = (int8_t)(v + bias[n]);
                        if (layer == 1) {
                            r = (int8_t)(r + hidA[(size_t)m * CORE + n]);
                            g_A2[(size_t)m * CORE + n] = r;
                        } else if (layer == 2) {
                            g_H2[(size_t)m * CORE + n] = r;
                            long oi = (long)m * CORE + n;
                            if (mode_out == 3) ((__nv_bfloat16*)Dout)[oi] = __float2bfloat16((float)r);
                            else               ((float*)Dout)[oi] = (float)r;
                        } else {
                            if (n < OUT_N) {
                                long oi = (long)BATCH * CORE + (long)m * OUT_N + n;
                                if (mode_out == 3) ((__nv_bfloat16*)Dout)[oi] = __float2bfloat16((float)r);
                                else               ((float*)Dout)[oi] = (float)r;
                            }
                        }
                    }
                }

        // ---- publish completion ----
        if (layer != 3) {
            __threadfence();
            __syncthreads();
            if (tid == 0) {
                if (layer == 1) atomicAdd(&g_rowdone[mblk], 1);
                else            atomicAdd(&g_row2done[mblk], 1);
            }
        }
    }
}

extern "C" void kernel_launch(void* const* d_in, const int* in_sizes, int n_in,
                              void* d_out, int out_size) {
    int idx[64];
    int cnt = (n_in < 64) ? n_in : 64;
    for (int i = 0; i < cnt; i++) idx[i] = i;
    for (int a = 1; a < cnt; a++) {
        int t = idx[a], b = a - 1;
        while (b >= 0 && in_sizes[idx[b]] < in_sizes[t]) { idx[b + 1] = idx[b]; b--; }
        idx[b + 1] = t;
    }
    const void *inputs = 0, *hiddens = 0, *Wi = 0, *ei = 0, *Wc = 0, *ec = 0;
    const void *Wo = 0, *eo = 0, *bo = 0, *ebo = 0;
    const void *bi = 0, *bc = 0, *ebi = 0, *ebc = 0;
    long unit = 1;
    if (cnt >= 14) {
        inputs = d_in[idx[0]]; hiddens = d_in[idx[1]];
        Wi = d_in[idx[2]]; ei = d_in[idx[3]];
        Wc = d_in[idx[4]]; ec = d_in[idx[5]];
        Wo = d_in[idx[6]]; eo = d_in[idx[7]];
        bo = d_in[idx[12]]; ebo = d_in[idx[13]];
        bool alpha = (idx[4] < idx[2]);
        if (alpha) { bc = d_in[idx[8]]; bi = d_in[idx[9]]; ebc = d_in[idx[10]]; ebi = d_in[idx[11]]; }
        else       { bi = d_in[idx[8]]; bc = d_in[idx[9]]; ebi = d_in[idx[10]]; ebc = d_in[idx[11]]; }
        unit = (long)in_sizes[idx[0]] / ((long)BATCH * IN_SZ);
        if (unit < 1) unit = 1;
    } else {
        Wi = d_in[0]; bi = d_in[1]; Wc = d_in[2]; bc = d_in[3];
        Wo = d_in[4]; bo = d_in[5]; ei = d_in[6]; ebi = d_in[7];
        ec = d_in[8]; ebc = d_in[9]; eo = d_in[10]; ebo = d_in[11];
        inputs = d_in[12]; hiddens = d_in[13];
    }
    const long total_out = (long)BATCH * CORE + (long)BATCH * OUT_N;
    int mode_out = 1;
    if ((long)out_size == 2 * total_out) mode_out = 3;

    static int s_attr_done = 0;
    if (!s_attr_done) {
        cudaFuncSetAttribute(gemm_all, cudaFuncAttributeMaxDynamicSharedMemorySize, SMEM_BYTES);
        s_attr_done = 1;
    }

    detect_mode<<<1, 256>>>(Wi, (int)unit);
    {
        long tot = (long)BATCH * IN_SZ + (long)BATCH * CORE;
        conv_acts<<<(unsigned)((tot + 255) / 256), 256>>>(inputs, hiddens);
    }
    prep_wb<<<TWI + TWC + TWO + 9, dim3(32, 8)>>>(Wi, ei, Wc, ec, Wo, eo,
                                                  bi, ebi, bc, ebc, bo, ebo);
    gemm_all<<<GRID_P, 256, SMEM_BYTES>>>((const int8_t*)inputs,
                                          (const int8_t*)hiddens,
                                          d_out, mode_out);
}

// round 15
// speedup vs baseline: 1.1536x; 1.1536x over previous
#include <cuda_runtime.h>
#include <cuda_bf16.h>
#include <stdint.h>
#include <math.h>

#define IN_SZ   3072
#define CORE    1024
#define OUT_N   100
#define OUT_PAD 128
#define BATCH   8192
#define STAGES  3
#define STG_OP  16384
#define SMEM_BYTES (STAGES * 2 * STG_OP)
#define SLOTS   296                 // 148 SM x 2 CTA
#define W2TILES 216                 // 512 - 296 wave-2 tiles
#define NKT1    24                  // K=3072 in 128B chunks
#define NKT2    8                   // K=1024 in 128B chunks
#define TOTC1   (W2TILES * NKT1)    // 5184
#define TOTC2   (W2TILES * NKT2)    // 1728

__device__ int g_mode;
__device__ int g_pacc[W2TILES * 16384];   // int32 partials, zero-maintained

__device__ __align__(16) int8_t g_WiT[CORE * IN_SZ];
__device__ __align__(16) int8_t g_WcT[CORE * CORE];
__device__ __align__(16) int8_t g_WoT[OUT_PAD * CORE];
__device__ __align__(16) int    g_bi[CORE];
__device__ __align__(16) int    g_bc[CORE];
__device__ __align__(16) int    g_bo[OUT_PAD];
__device__ __align__(16) int8_t g_in8[(size_t)BATCH * IN_SZ];
__device__ __align__(16) int8_t g_h8[(size_t)BATCH * CORE];
__device__ __align__(16) int8_t g_A2[(size_t)BATCH * CORE];
__device__ __align__(16) int8_t g_H2[(size_t)BATCH * CORE];

__device__ __forceinline__ uint32_t smem_u32(const void* p) {
    uint32_t a;
    asm("{ .reg .u64 t; cvta.to.shared.u64 t, %1; cvt.u32.u64 %0, t; }" : "=r"(a) : "l"(p));
    return a;
}
__device__ __forceinline__ void cpasync16(unsigned dst, const void* src) {
    asm volatile("cp.async.cg.shared.global [%0], [%1], 16;" :: "r"(dst), "l"(src));
}
__device__ __forceinline__ int ldval(const void* src, long i, int m) {
    if (m == 0) return (int)((const int8_t*)src)[i];
    if (m == 1) return (int)((const float*)src)[i];
    if (m == 2) return ((const int*)src)[i];
    return (int)__bfloat162float(((const __nv_bfloat16*)src)[i]);
}

__global__ void detect_mode(const void* w, int unit) {
    int t = threadIdx.x;
    if (unit == 2) { if (t == 0) g_mode = 3; return; }
    unsigned r = ((const unsigned*)w)[t * 101];
    int vi = (int)r;
    bool okI = (vi >= -10 && vi <= 10);
    float f = __int_as_float(r);
    bool okF = (isfinite(f) && f == truncf(f) && fabsf(f) <= 10.0f &&
                (f == 0.0f || fabsf(f) >= 1.0f));
    bool okB = true;
    for (int h = 0; h < 2; h++) {
        unsigned hf = (h == 0) ? (r & 0xFFFFu) : (r >> 16);
        float fb = __int_as_float(hf << 16);
        if (!(isfinite(fb) && fb == truncf(fb) && fabsf(fb) <= 10.0f &&
              (fb == 0.0f || fabsf(fb) >= 1.0f))) okB = false;
    }
    int aI = __syncthreads_and((int)okI);
    int aF = __syncthreads_and((int)okF);
    int aB = __syncthreads_and((int)okB);
    if (t == 0)
        g_mode = (unit == 4) ? (aI ? 2 : 1) : (aI ? 2 : (aF ? 1 : (aB ? 3 : 0)));
}

__global__ void conv_acts(const void* __restrict__ inp, const void* __restrict__ hid) {
    const int m = g_mode;
    if (m == 0) return;
    long i = (long)blockIdx.x * blockDim.x + threadIdx.x;
    const long NI = (long)BATCH * IN_SZ;
    if (i < NI) g_in8[i] = (int8_t)ldval(inp, i, m);
    else {
        long j = i - NI;
        if (j < (long)BATCH * CORE) g_h8[j] = (int8_t)ldval(hid, j, m);
    }
}

#define TWI 3072
#define TWC 1024
#define TWO 128
__global__ void prep_wb(const void* __restrict__ Wi, const void* __restrict__ ei,
                        const void* __restrict__ Wc, const void* __restrict__ ec,
                        const void* __restrict__ Wo, const void* __restrict__ eo,
                        const void* __restrict__ bi, const void* __restrict__ ebi,
                        const void* __restrict__ bc, const void* __restrict__ ebc,
                        const void* __restrict__ bo, const void* __restrict__ ebo) {
    const int m = g_mode;
    const int b = blockIdx.x;
    const int tx = threadIdx.x, ty = threadIdx.y;
    const void *W, *E;
    int8_t* dst;
    int Kdim, Ncols, kt, nt;
    if (b < TWI) {
        W = Wi; E = ei; dst = g_WiT; Kdim = IN_SZ; Ncols = CORE;
        kt = b % (IN_SZ / 32); nt = b / (IN_SZ / 32);
    } else if (b < TWI + TWC) {
        int r = b - TWI;
        W = Wc; E = ec; dst = g_WcT; Kdim = CORE; Ncols = CORE;
        kt = r % 32; nt = r / 32;
    } else if (b < TWI + TWC + TWO) {
        int r = b - TWI - TWC;
        W = Wo; E = eo; dst = g_WoT; Kdim = CORE; Ncols = OUT_N;
        kt = r % 32; nt = r / 32;
    } else {
        int t = (b - TWI - TWC - TWO) * 256 + ty * 32 + tx;
        if (t < CORE) g_bi[t] = (int)(int8_t)(ldval(bi, t, m) + ldval(ebi, t, m));
        else if (t < 2 * CORE) {
            int i = t - CORE;
            g_bc[i] = (int)(int8_t)(ldval(bc, i, m) + ldval(ebc, i, m));
        } else if (t < 2 * CORE + OUT_PAD) {
            int i = t - 2 * CORE;
            g_bo[i] = (i < OUT_N) ? (int)(int8_t)(ldval(bo, i, m) + ldval(ebo, i, m)) : 0;
        }
        return;
    }
    __shared__ int8_t s[32][33];
    const int kb = kt * 32, nb = nt * 32;
#pragma unroll
    for (int i = 0; i < 32; i += 8) {
        int k = kb + ty + i, n = nb + tx;
        int8_t v = 0;
        if (n < Ncols) {
            long idx = (long)k * Ncols + n;
            v = (int8_t)(ldval(W, idx, m) + ldval(E, idx, m));
        }
        s[ty + i][tx] = v;
    }
    __syncthreads();
#pragma unroll
    for (int i = 0; i < 32; i += 8) {
        int n = nb + ty + i, k = kb + tx;
        dst[(size_t)n * Kdim + k] = s[tx][ty + i];
    }
}

// ---------------- GEMM: wave1 = full tiles (direct), wave2 = balanced K-split (atomic) ----
template <int LAYER>
__global__ void __launch_bounds__(256, 2)
gemm_s8(const int8_t* __restrict__ rawA, const int8_t* __restrict__ convA,
        const int8_t* __restrict__ Bt, const int* __restrict__ bias,
        int8_t* __restrict__ Cs, void* __restrict__ Dout,
        const int8_t* __restrict__ rawH, const int8_t* __restrict__ convH,
        int mode_out) {
    extern __shared__ __align__(16) int8_t dyn[];
    const int K = (LAYER == 1) ? IN_SZ : CORE;
    const int nkt = (LAYER == 1) ? NKT1 : NKT2;

    const int8_t* A = (LAYER == 1 && g_mode != 0) ? convA : rawA;
    const int8_t* H = (LAYER == 1 && g_mode != 0) ? convH : rawH;

    const int bid = blockIdx.x;
    const int tid = threadIdx.x, lane = tid & 31, wid = tid >> 5;
    const int wm = (wid & 1) * 64, wn = (wid >> 1) * 32;
    const int r0  = tid >> 3;
    const int seg = (tid & 7) << 4;
    const int swz = seg ^ ((r0 & 7) << 4);
    const unsigned uS = smem_u32(dyn);
    const unsigned uB = uS + STAGES * STG_OP;

    // segments: direct full tile (wave1 / layer3) or 1-2 K-split segments (wave2)
    int sTile[2], sK0[2], sKn[2], nseg;
    bool direct;
    if (LAYER == 3 || bid < SLOTS) {
        direct = true; nseg = 1;
        sTile[0] = bid; sK0[0] = 0; sKn[0] = nkt;
    } else {
        direct = false; nseg = 0;
        const int TOT = (LAYER == 1) ? TOTC1 : TOTC2;
        const int j = bid - SLOTS;
        int c  = (int)(((long)j * TOT) / SLOTS);
        int ce = (int)(((long)(j + 1) * TOT) / SLOTS);
        while (c < ce) {
            int t = c / nkt, k0 = c % nkt;
            int kn = nkt - k0; if (kn > ce - c) kn = ce - c;
            sTile[nseg] = SLOTS + t; sK0[nseg] = k0; sKn[nseg] = kn;
            nseg++; c += kn;
        }
    }

    for (int si = 0; si < nseg; si++) {
        const int tile = sTile[si];
        const int mblk = (LAYER == 3) ? tile : (tile >> 3);
        const int nblk = (LAYER == 3) ? 0 : (tile & 7);
        const int m0 = mblk * 128, n0 = nblk * 128;
        const int kc0 = sK0[si], kcn = sKn[si];

        const int8_t* gA = A + (size_t)(m0 + r0) * K + seg + ((long)kc0 << 7);
        const int8_t* gB = Bt + (size_t)(n0 + r0) * K + seg + ((long)kc0 << 7);
        const long rs32 = 32L * K;

        int acc[4][4][4];
#pragma unroll
        for (int a = 0; a < 4; a++)
#pragma unroll
            for (int b = 0; b < 4; b++)
#pragma unroll
                for (int c2 = 0; c2 < 4; c2++) acc[a][b][c2] = 0;

#define LOADT(st, kt)                                                     \
        do {                                                              \
            const unsigned _a = uS + (st) * STG_OP;                       \
            const unsigned _b = uB + (st) * STG_OP;                       \
            const long _o = (long)(kt) << 7;                              \
            _Pragma("unroll")                                             \
            for (int _i = 0; _i < 4; _i++) {                              \
                const unsigned _d = (_i * 32 + r0) * 128 + swz;           \
                cpasync16(_a + _d, gA + _o + _i * rs32);                  \
                cpasync16(_b + _d, gB + _o + _i * rs32);                  \
            }                                                             \
            asm volatile("cp.async.commit_group;");                       \
        } while (0)

        LOADT(0, 0);
        if (kcn > 1) LOADT(1, 1);

        for (int kt = 0; kt < kcn; kt++) {
            const int cur = kt % STAGES;
            // FIX (R14 bug): on the LAST chunk only one group is pending, so
            // wait_group 1 was a no-op and mma consumed unarrived smem.
            if (kt + 1 < kcn) asm volatile("cp.async.wait_group 1;");
            else              asm volatile("cp.async.wait_group 0;");
            __syncthreads();
            if (kt + 2 < kcn) LOADT((kt + 2) % STAGES, kt + 2);
            const unsigned ab = uS + cur * STG_OP;
            const unsigned bb = uB + cur * STG_OP;
#pragma unroll
            for (int ks = 0; ks < 128; ks += 32) {
                uint32_t af[4][4], bf[4][2];
#pragma unroll
                for (int mf = 0; mf < 4; mf++) {
                    const int ra = wm + mf * 16 + (lane & 15);
                    const int ca = ks + ((lane >> 4) << 4);
                    const unsigned p = ab + ra * 128 + (ca ^ ((ra & 7) << 4));
                    asm volatile("ldmatrix.sync.aligned.m8n8.x4.shared.b16 {%0,%1,%2,%3}, [%4];"
                                 : "=r"(af[mf][0]), "=r"(af[mf][1]), "=r"(af[mf][2]), "=r"(af[mf][3]) : "r"(p));
                }
#pragma unroll
                for (int nf = 0; nf < 4; nf++) {
                    const int rb = wn + nf * 8 + (lane & 7);
                    const int cb = ks + (((lane >> 3) & 1) << 4);
                    const unsigned p = bb + rb * 128 + (cb ^ ((rb & 7) << 4));
                    asm volatile("ldmatrix.sync.aligned.m8n8.x2.shared.b16 {%0,%1}, [%2];"
                                 : "=r"(bf[nf][0]), "=r"(bf[nf][1]) : "r"(p));
                }
#pragma unroll
                for (int mf = 0; mf < 4; mf++)
#pragma unroll
                    for (int nf = 0; nf < 4; nf++)
                        asm volatile("mma.sync.aligned.m16n8k32.row.col.s32.s8.s8.s32 "
                                     "{%0,%1,%2,%3}, {%4,%5,%6,%7}, {%8,%9}, {%0,%1,%2,%3};"
                                     : "+r"(acc[mf][nf][0]), "+r"(acc[mf][nf][1]),
                                       "+r"(acc[mf][nf][2]), "+r"(acc[mf][nf][3])
                                     : "r"(af[mf][0]), "r"(af[mf][1]), "r"(af[mf][2]), "r"(af[mf][3]),
                                       "r"(bf[nf][0]), "r"(bf[nf][1]));
            }
        }
#undef LOADT
        asm volatile("cp.async.wait_group 0;");
        __syncthreads();   // smem reusable for next segment

        const int rr = lane >> 2, cq = (lane & 3) * 2;
        int* pacc = g_pacc + (long)(tile - SLOTS) * 16384;
#pragma unroll
        for (int mf = 0; mf < 4; mf++)
#pragma unroll
            for (int nf = 0; nf < 4; nf++)
#pragma unroll
                for (int half = 0; half < 2; half++)
#pragma unroll
                    for (int e = 0; e < 2; e++) {
                        const int ml = wm + mf * 16 + rr + half * 8;
                        const int nl = wn + nf * 8 + cq + e;
                        const int v = acc[mf][nf][half * 2 + e];
                        if (!direct) {
                            atomicAdd(&pacc[ml * 128 + nl], v);
                        } else {
                            const int m = m0 + ml, n = n0 + nl;
                            int8_t r = (int8_t)(v + bias[n]);
                            if (LAYER == 1) {
                                r = (int8_t)(r + H[(size_t)m * CORE + n]);
                                Cs[(size_t)m * CORE + n] = r;
                            } else if (LAYER == 2) {
                                Cs[(size_t)m * CORE + n] = r;
                                long oi = (long)m * CORE + n;
                                if (mode_out == 3) ((__nv_bfloat16*)Dout)[oi] = __float2bfloat16((float)r);
                                else               ((float*)Dout)[oi] = (float)r;
                            } else {
                                if (n < OUT_N) {
                                    long oi = (long)BATCH * CORE + (long)m * OUT_N + n;
                                    if (mode_out == 3) ((__nv_bfloat16*)Dout)[oi] = __float2bfloat16((float)r);
                                    else               ((float*)Dout)[oi] = (float)r;
                                }
                            }
                        }
                    }
    }
}

// finalize wave-2 tiles: apply bias/H, write outputs, RE-ZERO pacc
template <int LAYER>
__global__ void finalize(const int* __restrict__ bias, int8_t* __restrict__ Cs,
                         void* __restrict__ Dout,
                         const int8_t* __restrict__ rawH, const int8_t* __restrict__ convH,
                         int mode_out) {
    const int8_t* H = (LAYER == 1 && g_mode != 0) ? convH : rawH;
    long i = (long)blockIdx.x * blockDim.x + threadIdx.x;
    if (i >= (long)W2TILES * 16384) return;
    int t = (int)(i >> 14);
    int loc = (int)(i & 16383);
    int tile = SLOTS + t;
    int m = (tile >> 3) * 128 + (loc >> 7);
    int n = (tile & 7) * 128 + (loc & 127);
    int v = g_pacc[i];
    g_pacc[i] = 0;
    int8_t r = (int8_t)(v + bias[n]);
    if (LAYER == 1) {
        r = (int8_t)(r + H[(size_t)m * CORE + n]);
        Cs[(size_t)m * CORE + n] = r;
    } else {
        Cs[(size_t)m * CORE + n] = r;
        long oi = (long)m * CORE + n;
        if (mode_out == 3) ((__nv_bfloat16*)Dout)[oi] = __float2bfloat16((float)r);
        else               ((float*)Dout)[oi] = (float)r;
    }
}

extern "C" void kernel_launch(void* const* d_in, const int* in_sizes, int n_in,
                              void* d_out, int out_size) {
    int idx[64];
    int cnt = (n_in < 64) ? n_in : 64;
    for (int i = 0; i < cnt; i++) idx[i] = i;
    for (int a = 1; a < cnt; a++) {
        int t = idx[a], b = a - 1;
        while (b >= 0 && in_sizes[idx[b]] < in_sizes[t]) { idx[b + 1] = idx[b]; b--; }
        idx[b + 1] = t;
    }
    const void *inputs = 0, *hiddens = 0, *Wi = 0, *ei = 0, *Wc = 0, *ec = 0;
    const void *Wo = 0, *eo = 0, *bo = 0, *ebo = 0;
    const void *bi = 0, *bc = 0, *ebi = 0, *ebc = 0;
    long unit = 1;
    if (cnt >= 14) {
        inputs = d_in[idx[0]]; hiddens = d_in[idx[1]];
        Wi = d_in[idx[2]]; ei = d_in[idx[3]];
        Wc = d_in[idx[4]]; ec = d_in[idx[5]];
        Wo = d_in[idx[6]]; eo = d_in[idx[7]];
        bo = d_in[idx[12]]; ebo = d_in[idx[13]];
        bool alpha = (idx[4] < idx[2]);
        if (alpha) { bc = d_in[idx[8]]; bi = d_in[idx[9]]; ebc = d_in[idx[10]]; ebi = d_in[idx[11]]; }
        else       { bi = d_in[idx[8]]; bc = d_in[idx[9]]; ebi = d_in[idx[10]]; ebc = d_in[idx[11]]; }
        unit = (long)in_sizes[idx[0]] / ((long)BATCH * IN_SZ);
        if (unit < 1) unit = 1;
    } else {
        Wi = d_in[0]; bi = d_in[1]; Wc = d_in[2]; bc = d_in[3];
        Wo = d_in[4]; bo = d_in[5]; ei = d_in[6]; ebi = d_in[7];
        ec = d_in[8]; ebc = d_in[9]; eo = d_in[10]; ebo = d_in[11];
        inputs = d_in[12]; hiddens = d_in[13];
    }
    const long total_out = (long)BATCH * CORE + (long)BATCH * OUT_N;
    int mode_out = 1;
    if ((long)out_size == 2 * total_out) mode_out = 3;

    void *pWiT, *pWcT, *pWoT, *pbi, *pbc, *pbo, *pin8, *ph8, *pA2, *pH2;
    cudaGetSymbolAddress(&pWiT, g_WiT);
    cudaGetSymbolAddress(&pWcT, g_WcT);
    cudaGetSymbolAddress(&pWoT, g_WoT);
    cudaGetSymbolAddress(&pbi, g_bi);
    cudaGetSymbolAddress(&pbc, g_bc);
    cudaGetSymbolAddress(&pbo, g_bo);
    cudaGetSymbolAddress(&pin8, g_in8);
    cudaGetSymbolAddress(&ph8, g_h8);
    cudaGetSymbolAddress(&pA2, g_A2);
    cudaGetSymbolAddress(&pH2, g_H2);

    static int s_attr_done = 0;
    if (!s_attr_done) {
        cudaFuncSetAttribute(gemm_s8<1>, cudaFuncAttributeMaxDynamicSharedMemorySize, SMEM_BYTES);
        cudaFuncSetAttribute(gemm_s8<2>, cudaFuncAttributeMaxDynamicSharedMemorySize, SMEM_BYTES);
        cudaFuncSetAttribute(gemm_s8<3>, cudaFuncAttributeMaxDynamicSharedMemorySize, SMEM_BYTES);
        s_attr_done = 1;
    }

    detect_mode<<<1, 256>>>(Wi, (int)unit);
    {
        long tot = (long)BATCH * IN_SZ + (long)BATCH * CORE;
        conv_acts<<<(unsigned)((tot + 255) / 256), 256>>>(inputs, hiddens);
    }
    prep_wb<<<TWI + TWC + TWO + 9, dim3(32, 8)>>>(Wi, ei, Wc, ec, Wo, eo,
                                                  bi, ebi, bc, ebc, bo, ebo);

    const unsigned finGrid = (unsigned)(((long)W2TILES * 16384 + 255) / 256);

    gemm_s8<1><<<SLOTS * 2, 256, SMEM_BYTES>>>(
        (const int8_t*)inputs, (const int8_t*)pin8,
        (const int8_t*)pWiT, (const int*)pbi,
        (int8_t*)pA2, nullptr,
        (const int8_t*)hiddens, (const int8_t*)ph8, mode_out);
    finalize<1><<<finGrid, 256>>>((const int*)pbi, (int8_t*)pA2, nullptr,
                                  (const int8_t*)hiddens, (const int8_t*)ph8, mode_out);

    gemm_s8<2><<<SLOTS * 2, 256, SMEM_BYTES>>>(
        (const int8_t*)pA2, (const int8_t*)pA2,
        (const int8_t*)pWcT, (const int*)pbc,
        (int8_t*)pH2, d_out, nullptr, nullptr, mode_out);
    finalize<2><<<finGrid, 256>>>((const int*)pbc, (int8_t*)pH2, d_out,
                                  nullptr, nullptr, mode_out);

    gemm_s8<3><<<64, 256, SMEM_BYTES>>>(
        (const int8_t*)pH2, (const int8_t*)pH2,
        (const int8_t*)pWoT, (const int*)pbo,
        nullptr, d_out, nullptr, nullptr, mode_out);
}

// round 16
// speedup vs baseline: 1.2390x; 1.0741x over previous
#include <cuda_runtime.h>
#include <cuda_bf16.h>
#include <stdint.h>
#include <math.h>

#define IN_SZ   3072
#define CORE    1024
#define OUT_N   100
#define OUT_PAD 128
#define BATCH   8192
#define STAGES  3
#define STG_OP  16384
#define SMEM_BYTES (STAGES * 2 * STG_OP)
#define SLOTS   296                 // 148 SM x 2 CTA
#define W2TILES 216                 // 512 - 296 wave-2 tiles
#define NKT1    24
#define NKT2    8
#define NKT3    8
#define TOTC1   (W2TILES * NKT1)    // 5184
#define TOTC2   (W2TILES * NKT2)    // 1728
#define TOTC3   (64 * NKT3)         // 512 (whole layer 3 K-split)

__device__ int g_mode;
__device__ int g_pacc[W2TILES * 16384];   // int32 partials, zero-maintained

__device__ __align__(16) int8_t g_WiT[CORE * IN_SZ];
__device__ __align__(16) int8_t g_WcT[CORE * CORE];
__device__ __align__(16) int8_t g_WoT[OUT_PAD * CORE];
__device__ __align__(16) int    g_bi[CORE];
__device__ __align__(16) int    g_bc[CORE];
__device__ __align__(16) int    g_bo[OUT_PAD];
__device__ __align__(16) int8_t g_in8[(size_t)BATCH * IN_SZ];
__device__ __align__(16) int8_t g_h8[(size_t)BATCH * CORE];
__device__ __align__(16) int8_t g_A2[(size_t)BATCH * CORE];
__device__ __align__(16) int8_t g_H2[(size_t)BATCH * CORE];

__device__ __forceinline__ uint32_t smem_u32(const void* p) {
    uint32_t a;
    asm("{ .reg .u64 t; cvta.to.shared.u64 t, %1; cvt.u32.u64 %0, t; }" : "=r"(a) : "l"(p));
    return a;
}
__device__ __forceinline__ void cpasync16(unsigned dst, const void* src) {
    asm volatile("cp.async.cg.shared.global [%0], [%1], 16;" :: "r"(dst), "l"(src));
}
__device__ __forceinline__ int ldval(const void* src, long i, int m) {
    if (m == 0) return (int)((const int8_t*)src)[i];
    if (m == 1) return (int)((const float*)src)[i];
    if (m == 2) return ((const int*)src)[i];
    return (int)__bfloat162float(((const __nv_bfloat16*)src)[i]);
}

__global__ void detect_mode(const void* w, int unit) {
    int t = threadIdx.x;
    if (unit == 2) { if (t == 0) g_mode = 3; return; }
    unsigned r = ((const unsigned*)w)[t * 101];
    int vi = (int)r;
    bool okI = (vi >= -10 && vi <= 10);
    float f = __int_as_float(r);
    bool okF = (isfinite(f) && f == truncf(f) && fabsf(f) <= 10.0f &&
                (f == 0.0f || fabsf(f) >= 1.0f));
    bool okB = true;
    for (int h = 0; h < 2; h++) {
        unsigned hf = (h == 0) ? (r & 0xFFFFu) : (r >> 16);
        float fb = __int_as_float(hf << 16);
        if (!(isfinite(fb) && fb == truncf(fb) && fabsf(fb) <= 10.0f &&
              (fb == 0.0f || fabsf(fb) >= 1.0f))) okB = false;
    }
    int aI = __syncthreads_and((int)okI);
    int aF = __syncthreads_and((int)okF);
    int aB = __syncthreads_and((int)okB);
    if (t == 0)
        g_mode = (unit == 4) ? (aI ? 2 : 1) : (aI ? 2 : (aF ? 1 : (aB ? 3 : 0)));
}

// grid-stride; cheap when mode==0 (only 2048 blocks dispatched)
__global__ void conv_acts(const void* __restrict__ inp, const void* __restrict__ hid) {
    const int m = g_mode;
    if (m == 0) return;
    const long NI = (long)BATCH * IN_SZ;
    const long NT = NI + (long)BATCH * CORE;
    const long stride = (long)gridDim.x * blockDim.x;
    for (long i = (long)blockIdx.x * blockDim.x + threadIdx.x; i < NT; i += stride) {
        if (i < NI) g_in8[i] = (int8_t)ldval(inp, i, m);
        else        g_h8[i - NI] = (int8_t)ldval(hid, i - NI, m);
    }
}

#define TWI 3072
#define TWC 1024
#define TWO 128
__global__ void prep_wb(const void* __restrict__ Wi, const void* __restrict__ ei,
                        const void* __restrict__ Wc, const void* __restrict__ ec,
                        const void* __restrict__ Wo, const void* __restrict__ eo,
                        const void* __restrict__ bi, const void* __restrict__ ebi,
                        const void* __restrict__ bc, const void* __restrict__ ebc,
                        const void* __restrict__ bo, const void* __restrict__ ebo) {
    const int m = g_mode;
    const int b = blockIdx.x;
    const int tx = threadIdx.x, ty = threadIdx.y;
    const void *W, *E;
    int8_t* dst;
    int Kdim, Ncols, kt, nt;
    if (b < TWI) {
        W = Wi; E = ei; dst = g_WiT; Kdim = IN_SZ; Ncols = CORE;
        kt = b % (IN_SZ / 32); nt = b / (IN_SZ / 32);
    } else if (b < TWI + TWC) {
        int r = b - TWI;
        W = Wc; E = ec; dst = g_WcT; Kdim = CORE; Ncols = CORE;
        kt = r % 32; nt = r / 32;
    } else if (b < TWI + TWC + TWO) {
        int r = b - TWI - TWC;
        W = Wo; E = eo; dst = g_WoT; Kdim = CORE; Ncols = OUT_N;
        kt = r % 32; nt = r / 32;
    } else {
        int t = (b - TWI - TWC - TWO) * 256 + ty * 32 + tx;
        if (t < CORE) g_bi[t] = (int)(int8_t)(ldval(bi, t, m) + ldval(ebi, t, m));
        else if (t < 2 * CORE) {
            int i = t - CORE;
            g_bc[i] = (int)(int8_t)(ldval(bc, i, m) + ldval(ebc, i, m));
        } else if (t < 2 * CORE + OUT_PAD) {
            int i = t - 2 * CORE;
            g_bo[i] = (i < OUT_N) ? (int)(int8_t)(ldval(bo, i, m) + ldval(ebo, i, m)) : 0;
        }
        return;
    }
    __shared__ int8_t s[32][33];
    const int kb = kt * 32, nb = nt * 32;
#pragma unroll
    for (int i = 0; i < 32; i += 8) {
        int k = kb + ty + i, n = nb + tx;
        int8_t v = 0;
        if (n < Ncols) {
            long idx = (long)k * Ncols + n;
            v = (int8_t)(ldval(W, idx, m) + ldval(E, idx, m));
        }
        s[ty + i][tx] = v;
    }
    __syncthreads();
#pragma unroll
    for (int i = 0; i < 32; i += 8) {
        int n = nb + ty + i, k = kb + tx;
        dst[(size_t)n * Kdim + k] = s[tx][ty + i];
    }
}

// ---------------- GEMM ----------------
// L1/L2: wave1 = 296 direct tiles, wave2 = 296 balanced K-split jobs (atomic).
// L3: fully K-split over 296 jobs (atomic), finalize<3> applies bias.
template <int LAYER>
__global__ void __launch_bounds__(256, 2)
gemm_s8(const int8_t* __restrict__ rawA, const int8_t* __restrict__ convA,
        const int8_t* __restrict__ Bt, const int* __restrict__ bias,
        int8_t* __restrict__ Cs, void* __restrict__ Dout,
        const int8_t* __restrict__ rawH, const int8_t* __restrict__ convH,
        int mode_out) {
    extern __shared__ __align__(16) int8_t dyn[];
    const int K = (LAYER == 1) ? IN_SZ : CORE;
    const int nkt = (LAYER == 1) ? NKT1 : ((LAYER == 2) ? NKT2 : NKT3);

    const int8_t* A = (LAYER == 1 && g_mode != 0) ? convA : rawA;
    const int8_t* H = (LAYER == 1 && g_mode != 0) ? convH : rawH;

    const int bid = blockIdx.x;
    const int tid = threadIdx.x, lane = tid & 31, wid = tid >> 5;
    const int wm = (wid & 1) * 64, wn = (wid >> 1) * 32;
    const int r0  = tid >> 3;
    const int seg = (tid & 7) << 4;
    const int swz = seg ^ ((r0 & 7) << 4);
    const unsigned uS = smem_u32(dyn);
    const unsigned uB = uS + STAGES * STG_OP;

    // segments: direct full tile or 1-2 K-split segments
    int sTile[2], sK0[2], sKn[2], nseg;
    bool direct;
    if (LAYER != 3 && bid < SLOTS) {
        direct = true; nseg = 1;
        sTile[0] = bid; sK0[0] = 0; sKn[0] = nkt;
    } else {
        direct = false; nseg = 0;
        const int TOT = (LAYER == 1) ? TOTC1 : ((LAYER == 2) ? TOTC2 : TOTC3);
        const int j = (LAYER == 3) ? bid : (bid - SLOTS);
        const int base = (LAYER == 3) ? 0 : SLOTS;
        int c  = (int)(((long)j * TOT) / SLOTS);
        int ce = (int)(((long)(j + 1) * TOT) / SLOTS);
        while (c < ce) {
            int t = c / nkt, k0 = c % nkt;
            int kn = nkt - k0; if (kn > ce - c) kn = ce - c;
            sTile[nseg] = base + t; sK0[nseg] = k0; sKn[nseg] = kn;
            nseg++; c += kn;
        }
    }

    for (int si = 0; si < nseg; si++) {
        const int tile = sTile[si];
        const int mblk = (LAYER == 3) ? tile : (tile >> 3);
        const int nblk = (LAYER == 3) ? 0 : (tile & 7);
        const int m0 = mblk * 128, n0 = nblk * 128;
        const int kc0 = sK0[si], kcn = sKn[si];

        const int8_t* gA = A + (size_t)(m0 + r0) * K + seg + ((long)kc0 << 7);
        const int8_t* gB = Bt + (size_t)(n0 + r0) * K + seg + ((long)kc0 << 7);
        const long rs32 = 32L * K;

        int acc[4][4][4];
#pragma unroll
        for (int a = 0; a < 4; a++)
#pragma unroll
            for (int b = 0; b < 4; b++)
#pragma unroll
                for (int c2 = 0; c2 < 4; c2++) acc[a][b][c2] = 0;

#define LOADT(st, kt)                                                     \
        do {                                                              \
            const unsigned _a = uS + (st) * STG_OP;                       \
            const unsigned _b = uB + (st) * STG_OP;                       \
            const long _o = (long)(kt) << 7;                              \
            _Pragma("unroll")                                             \
            for (int _i = 0; _i < 4; _i++) {                              \
                const unsigned _d = (_i * 32 + r0) * 128 + swz;           \
                cpasync16(_a + _d, gA + _o + _i * rs32);                  \
                cpasync16(_b + _d, gB + _o + _i * rs32);                  \
            }                                                             \
            asm volatile("cp.async.commit_group;");                       \
        } while (0)

        LOADT(0, 0);
        if (kcn > 1) LOADT(1, 1);

        for (int kt = 0; kt < kcn; kt++) {
            const int cur = kt % STAGES;
            // last chunk: only one group pending -> must drain fully
            if (kt + 1 < kcn) asm volatile("cp.async.wait_group 1;");
            else              asm volatile("cp.async.wait_group 0;");
            __syncthreads();
            if (kt + 2 < kcn) LOADT((kt + 2) % STAGES, kt + 2);
            const unsigned ab = uS + cur * STG_OP;
            const unsigned bb = uB + cur * STG_OP;
#pragma unroll
            for (int ks = 0; ks < 128; ks += 32) {
                uint32_t af[4][4], bf[4][2];
#pragma unroll
                for (int mf = 0; mf < 4; mf++) {
                    const int ra = wm + mf * 16 + (lane & 15);
                    const int ca = ks + ((lane >> 4) << 4);
                    const unsigned p = ab + ra * 128 + (ca ^ ((ra & 7) << 4));
                    asm volatile("ldmatrix.sync.aligned.m8n8.x4.shared.b16 {%0,%1,%2,%3}, [%4];"
                                 : "=r"(af[mf][0]), "=r"(af[mf][1]), "=r"(af[mf][2]), "=r"(af[mf][3]) : "r"(p));
                }
#pragma unroll
                for (int nf = 0; nf < 4; nf++) {
                    const int rb = wn + nf * 8 + (lane & 7);
                    const int cb = ks + (((lane >> 3) & 1) << 4);
                    const unsigned p = bb + rb * 128 + (cb ^ ((rb & 7) << 4));
                    asm volatile("ldmatrix.sync.aligned.m8n8.x2.shared.b16 {%0,%1}, [%2];"
                                 : "=r"(bf[nf][0]), "=r"(bf[nf][1]) : "r"(p));
                }
#pragma unroll
                for (int mf = 0; mf < 4; mf++)
#pragma unroll
                    for (int nf = 0; nf < 4; nf++)
                        asm volatile("mma.sync.aligned.m16n8k32.row.col.s32.s8.s8.s32 "
                                     "{%0,%1,%2,%3}, {%4,%5,%6,%7}, {%8,%9}, {%0,%1,%2,%3};"
                                     : "+r"(acc[mf][nf][0]), "+r"(acc[mf][nf][1]),
                                       "+r"(acc[mf][nf][2]), "+r"(acc[mf][nf][3])
                                     : "r"(af[mf][0]), "r"(af[mf][1]), "r"(af[mf][2]), "r"(af[mf][3]),
                                       "r"(bf[nf][0]), "r"(bf[nf][1]));
            }
        }
#undef LOADT
        asm volatile("cp.async.wait_group 0;");
        __syncthreads();

        const int rr = lane >> 2, cq = (lane & 3) * 2;
        const int paccTile = (LAYER == 3) ? tile : (tile - SLOTS);
        int* pacc = g_pacc + (long)paccTile * 16384;
#pragma unroll
        for (int mf = 0; mf < 4; mf++)
#pragma unroll
            for (int nf = 0; nf < 4; nf++)
#pragma unroll
                for (int half = 0; half < 2; half++)
#pragma unroll
                    for (int e = 0; e < 2; e++) {
                        const int ml = wm + mf * 16 + rr + half * 8;
                        const int nl = wn + nf * 8 + cq + e;
                        const int v = acc[mf][nf][half * 2 + e];
                        if (!direct) {
                            atomicAdd(&pacc[ml * 128 + nl], v);
                        } else {
                            const int m = m0 + ml, n = n0 + nl;
                            int8_t r = (int8_t)(v + bias[n]);
                            if (LAYER == 1) {
                                r = (int8_t)(r + H[(size_t)m * CORE + n]);
                                Cs[(size_t)m * CORE + n] = r;
                            } else {
                                Cs[(size_t)m * CORE + n] = r;
                                long oi = (long)m * CORE + n;
                                if (mode_out == 3) ((__nv_bfloat16*)Dout)[oi] = __float2bfloat16((float)r);
                                else               ((float*)Dout)[oi] = (float)r;
                            }
                        }
                    }
    }
}

// finalize K-split tiles: apply bias (+H / output write), RE-ZERO pacc
template <int LAYER>
__global__ void finalize(const int* __restrict__ bias, int8_t* __restrict__ Cs,
                         void* __restrict__ Dout,
                         const int8_t* __restrict__ rawH, const int8_t* __restrict__ convH,
                         int mode_out) {
    const int8_t* H = (LAYER == 1 && g_mode != 0) ? convH : rawH;
    const long NTOT = (LAYER == 3) ? (64L * 16384) : ((long)W2TILES * 16384);
    long i = (long)blockIdx.x * blockDim.x + threadIdx.x;
    if (i >= NTOT) return;
    int t = (int)(i >> 14);
    int loc = (int)(i & 16383);
    int v = g_pacc[i];
    g_pacc[i] = 0;
    int m, n;
    if (LAYER == 3) {
        m = t * 128 + (loc >> 7);
        n = loc & 127;
        if (n >= OUT_N) return;
        int8_t r = (int8_t)(v + bias[n]);
        long oi = (long)BATCH * CORE + (long)m * OUT_N + n;
        if (mode_out == 3) ((__nv_bfloat16*)Dout)[oi] = __float2bfloat16((float)r);
        else               ((float*)Dout)[oi] = (float)r;
        return;
    }
    int tile = SLOTS + t;
    m = (tile >> 3) * 128 + (loc >> 7);
    n = (tile & 7) * 128 + (loc & 127);
    int8_t r = (int8_t)(v + bias[n]);
    if (LAYER == 1) {
        r = (int8_t)(r + H[(size_t)m * CORE + n]);
        Cs[(size_t)m * CORE + n] = r;
    } else {
        Cs[(size_t)m * CORE + n] = r;
        long oi = (long)m * CORE + n;
        if (mode_out == 3) ((__nv_bfloat16*)Dout)[oi] = __float2bfloat16((float)r);
        else               ((float*)Dout)[oi] = (float)r;
    }
}

extern "C" void kernel_launch(void* const* d_in, const int* in_sizes, int n_in,
                              void* d_out, int out_size) {
    int idx[64];
    int cnt = (n_in < 64) ? n_in : 64;
    for (int i = 0; i < cnt; i++) idx[i] = i;
    for (int a = 1; a < cnt; a++) {
        int t = idx[a], b = a - 1;
        while (b >= 0 && in_sizes[idx[b]] < in_sizes[t]) { idx[b + 1] = idx[b]; b--; }
        idx[b + 1] = t;
    }
    const void *inputs = 0, *hiddens = 0, *Wi = 0, *ei = 0, *Wc = 0, *ec = 0;
    const void *Wo = 0, *eo = 0, *bo = 0, *ebo = 0;
    const void *bi = 0, *bc = 0, *ebi = 0, *ebc = 0;
    long unit = 1;
    if (cnt >= 14) {
        inputs = d_in[idx[0]]; hiddens = d_in[idx[1]];
        Wi = d_in[idx[2]]; ei = d_in[idx[3]];
        Wc = d_in[idx[4]]; ec = d_in[idx[5]];
        Wo = d_in[idx[6]]; eo = d_in[idx[7]];
        bo = d_in[idx[12]]; ebo = d_in[idx[13]];
        bool alpha = (idx[4] < idx[2]);
        if (alpha) { bc = d_in[idx[8]]; bi = d_in[idx[9]]; ebc = d_in[idx[10]]; ebi = d_in[idx[11]]; }
        else       { bi = d_in[idx[8]]; bc = d_in[idx[9]]; ebi = d_in[idx[10]]; ebc = d_in[idx[11]]; }
        unit = (long)in_sizes[idx[0]] / ((long)BATCH * IN_SZ);
        if (unit < 1) unit = 1;
    } else {
        Wi = d_in[0]; bi = d_in[1]; Wc = d_in[2]; bc = d_in[3];
        Wo = d_in[4]; bo = d_in[5]; ei = d_in[6]; ebi = d_in[7];
        ec = d_in[8]; ebc = d_in[9]; eo = d_in[10]; ebo = d_in[11];
        inputs = d_in[12]; hiddens = d_in[13];
    }
    const long total_out = (long)BATCH * CORE + (long)BATCH * OUT_N;
    int mode_out = 1;
    if ((long)out_size == 2 * total_out) mode_out = 3;

    void *pWiT, *pWcT, *pWoT, *pbi, *pbc, *pbo, *pin8, *ph8, *pA2, *pH2;
    cudaGetSymbolAddress(&pWiT, g_WiT);
    cudaGetSymbolAddress(&pWcT, g_WcT);
    cudaGetSymbolAddress(&pWoT, g_WoT);
    cudaGetSymbolAddress(&pbi, g_bi);
    cudaGetSymbolAddress(&pbc, g_bc);
    cudaGetSymbolAddress(&pbo, g_bo);
    cudaGetSymbolAddress(&pin8, g_in8);
    cudaGetSymbolAddress(&ph8, g_h8);
    cudaGetSymbolAddress(&pA2, g_A2);
    cudaGetSymbolAddress(&pH2, g_H2);

    static int s_attr_done = 0;
    if (!s_attr_done) {
        cudaFuncSetAttribute(gemm_s8<1>, cudaFuncAttributeMaxDynamicSharedMemorySize, SMEM_BYTES);
        cudaFuncSetAttribute(gemm_s8<2>, cudaFuncAttributeMaxDynamicSharedMemorySize, SMEM_BYTES);
        cudaFuncSetAttribute(gemm_s8<3>, cudaFuncAttributeMaxDynamicSharedMemorySize, SMEM_BYTES);
        s_attr_done = 1;
    }

    detect_mode<<<1, 256>>>(Wi, (int)unit);
    conv_acts<<<2048, 256>>>(inputs, hiddens);
    prep_wb<<<TWI + TWC + TWO + 9, dim3(32, 8)>>>(Wi, ei, Wc, ec, Wo, eo,
                                                  bi, ebi, bc, ebc, bo, ebo);

    const unsigned finGrid12 = (unsigned)(((long)W2TILES * 16384 + 255) / 256);
    const unsigned finGrid3  = (unsigned)((64L * 16384 + 255) / 256);

    gemm_s8<1><<<SLOTS * 2, 256, SMEM_BYTES>>>(
        (const int8_t*)inputs, (const int8_t*)pin8,
        (const int8_t*)pWiT, (const int*)pbi,
        (int8_t*)pA2, nullptr,
        (const int8_t*)hiddens, (const int8_t*)ph8, mode_out);
    finalize<1><<<finGrid12, 256>>>((const int*)pbi, (int8_t*)pA2, nullptr,
                                    (const int8_t*)hiddens, (const int8_t*)ph8, mode_out);

    gemm_s8<2><<<SLOTS * 2, 256, SMEM_BYTES>>>(
        (const int8_t*)pA2, (const int8_t*)pA2,
        (const int8_t*)pWcT, (const int*)pbc,
        (int8_t*)pH2, d_out, nullptr, nullptr, mode_out);
    finalize<2><<<finGrid12, 256>>>((const int*)pbc, (int8_t*)pH2, d_out,
                                    nullptr, nullptr, mode_out);

    gemm_s8<3><<<SLOTS, 256, SMEM_BYTES>>>(
        (const int8_t*)pH2, (const int8_t*)pH2,
        (const int8_t*)pWoT, (const int*)pbo,
        nullptr, d_out, nullptr, nullptr, mode_out);
    finalize<3><<<finGrid3, 256>>>((const int*)pbo, nullptr, d_out,
                                   nullptr, nullptr, mode_out);
}